// round 2
// baseline (speedup 1.0000x reference)
#include <cuda_runtime.h>

// ---------------------------------------------------------------------------
// MS-SSIM, 4 levels, 11-tap Gaussian (sigma=1.5), VALID padding.
// X, Y: [16, 3, 512, 512] fp32. Output: 16 fp32 (1 - ms_ssim per batch).
// ---------------------------------------------------------------------------

#define KW   11
#define TILE 32
#define IT   (TILE + KW - 1)   // 42
#define NB   16
#define NC   3

// Gaussian weights (sigma=1.5, k=11, normalized) — precomputed.
__constant__ float c_g[KW] = {
    0.00102838f, 0.00759875f, 0.03600077f, 0.10936069f, 0.21300553f,
    0.26601174f,
    0.21300553f, 0.10936069f, 0.03600077f, 0.00759875f, 0.00102838f
};

// Scratch for downsampled pyramids (allocation-free: __device__ globals).
__device__ float g_X1[NB * NC * 256 * 256];
__device__ float g_Y1[NB * NC * 256 * 256];
__device__ float g_X2[NB * NC * 128 * 128];
__device__ float g_Y2[NB * NC * 128 * 128];
__device__ float g_X3[NB * NC * 64 * 64];
__device__ float g_Y3[NB * NC * 64 * 64];
// Per-(level, batch) accumulators.
__device__ double g_acc[4 * NB];

__global__ void zero_acc_kernel() {
    int i = threadIdx.x;
    if (i < 4 * NB) g_acc[i] = 0.0;
}

// Fused per-level SSIM kernel: separable blur of (X, Y, X^2, Y^2, XY) + SSIM
// map + block-level reduction into g_acc[level*NB + b].
// Grid: (tilesX * tilesY, NC, NB), block: (32, 8).
__global__ __launch_bounds__(256) void ssim_level_kernel(
    const float* __restrict__ X, const float* __restrict__ Y,
    int H, int W, int outH, int outW, int tilesX,
    int level, int isLast)
{
    __shared__ float sx[IT][IT + 2];
    __shared__ float sy[IT][IT + 2];
    __shared__ float hb[5][IT][TILE + 1];
    __shared__ float red[256];

    const int b = blockIdx.z;
    const int c = blockIdx.y;
    const int tile = blockIdx.x;
    const int tx = tile % tilesX;
    const int ty = tile / tilesX;
    const int ix0 = tx * TILE;
    const int iy0 = ty * TILE;

    const float* __restrict__ Xp = X + (size_t)(b * NC + c) * H * W;
    const float* __restrict__ Yp = Y + (size_t)(b * NC + c) * H * W;

    const int tid = threadIdx.y * 32 + threadIdx.x;

    // Phase 0: cooperative load of 42x42 halo tiles (clamped; out-of-range
    // values only feed outputs that are bounds-checked away).
    #pragma unroll 4
    for (int i = tid; i < IT * IT; i += 256) {
        int r  = i / IT;
        int cc = i - r * IT;
        int gy = min(iy0 + r,  H - 1);
        int gx = min(ix0 + cc, W - 1);
        sx[r][cc] = Xp[gy * W + gx];
        sy[r][cc] = Yp[gy * W + gx];
    }
    __syncthreads();

    // Phase 1: horizontal 11-tap blur of the 5 quantities.
    for (int i = tid; i < IT * TILE; i += 256) {
        int r  = i / TILE;
        int cc = i - r * TILE;
        float s0 = 0.f, s1 = 0.f, s2 = 0.f, s3 = 0.f, s4 = 0.f;
        #pragma unroll
        for (int k = 0; k < KW; k++) {
            float gk = c_g[k];
            float xv = sx[r][cc + k];
            float yv = sy[r][cc + k];
            s0 = fmaf(gk, xv, s0);
            s1 = fmaf(gk, yv, s1);
            s2 = fmaf(gk * xv, xv, s2);
            s3 = fmaf(gk * yv, yv, s3);
            s4 = fmaf(gk * xv, yv, s4);
        }
        hb[0][r][cc] = s0;
        hb[1][r][cc] = s1;
        hb[2][r][cc] = s2;
        hb[3][r][cc] = s3;
        hb[4][r][cc] = s4;
    }
    __syncthreads();

    // Phase 2: vertical 11-tap blur + SSIM math; each thread does 4 rows.
    const float C1 = 1e-4f;   // (0.01*1)^2
    const float C2 = 9e-4f;   // (0.03*1)^2
    float local = 0.f;
    const int lx = threadIdx.x;
    #pragma unroll
    for (int j = 0; j < 4; j++) {
        int ly = threadIdx.y + j * 8;
        int ox = ix0 + lx;
        int oy = iy0 + ly;
        if (ox < outW && oy < outH) {
            float mu1 = 0.f, mu2 = 0.f, xx = 0.f, yy = 0.f, xy = 0.f;
            #pragma unroll
            for (int k = 0; k < KW; k++) {
                float gk = c_g[k];
                mu1 = fmaf(gk, hb[0][ly + k][lx], mu1);
                mu2 = fmaf(gk, hb[1][ly + k][lx], mu2);
                xx  = fmaf(gk, hb[2][ly + k][lx], xx);
                yy  = fmaf(gk, hb[3][ly + k][lx], yy);
                xy  = fmaf(gk, hb[4][ly + k][lx], xy);
            }
            float s1q = xx - mu1 * mu1;
            float s2q = yy - mu2 * mu2;
            float s12 = xy - mu1 * mu2;
            float cs = (2.f * s12 + C2) / (s1q + s2q + C2);
            cs = fmaxf(cs, 0.f);
            if (isLast) {
                float lum = (2.f * mu1 * mu2 + C1) /
                            (mu1 * mu1 + mu2 * mu2 + C1);
                local += lum * cs;
            } else {
                local += cs;
            }
        }
    }

    // Block reduction.
    red[tid] = local;
    __syncthreads();
    #pragma unroll
    for (int s = 128; s > 0; s >>= 1) {
        if (tid < s) red[tid] += red[tid + s];
        __syncthreads();
    }
    if (tid == 0) {
        atomicAdd(&g_acc[level * NB + b], (double)red[0]);
    }
}

// 2x2 average pool for both images at once. H, W are input dims (even).
__global__ void pool2_kernel(const float* __restrict__ Xin,
                             const float* __restrict__ Yin,
                             float* __restrict__ Xout,
                             float* __restrict__ Yout,
                             int H, int W)
{
    int oW = W >> 1, oH = H >> 1;
    int total = NB * NC * oH * oW;
    int idx = blockIdx.x * blockDim.x + threadIdx.x;
    if (idx >= total) return;
    int ox = idx % oW;
    int t  = idx / oW;
    int oy = t % oH;
    int ic = t / oH;                 // fused (b*NC + c)
    const float* xp = Xin + (size_t)ic * H * W;
    const float* yp = Yin + (size_t)ic * H * W;
    int i0 = (oy * 2) * W + ox * 2;
    int i1 = i0 + W;
    float xv = 0.25f * (xp[i0] + xp[i0 + 1] + xp[i1] + xp[i1 + 1]);
    float yv = 0.25f * (yp[i0] + yp[i0 + 1] + yp[i1] + yp[i1 + 1]);
    Xout[(size_t)ic * oH * oW + oy * oW + ox] = xv;
    Yout[(size_t)ic * oH * oW + oy * oW + ox] = yv;
}

__global__ void finalize_kernel(float* __restrict__ out) {
    int b = threadIdx.x;
    if (b >= NB) return;
    // Per-level element counts: NC * (H-10)^2
    const double counts[4] = {
        3.0 * 502.0 * 502.0,
        3.0 * 246.0 * 246.0,
        3.0 * 118.0 * 118.0,
        3.0 * 54.0  * 54.0
    };
    const double wraw[4] = {0.0448, 0.2856, 0.3001, 0.2363};
    const double wsum = 0.0448 + 0.2856 + 0.3001 + 0.2363;
    double s = 0.0;
    #pragma unroll
    for (int l = 0; l < 4; l++) {
        double v = g_acc[l * NB + b] / counts[l];
        v = v > 1e-8 ? v : 1e-8;
        s += (wraw[l] / wsum) * log(v);
    }
    out[b] = (float)(1.0 - exp(s));
}

static inline int cdiv(int a, int b) { return (a + b - 1) / b; }

extern "C" void kernel_launch(void* const* d_in, const int* in_sizes, int n_in,
                              void* d_out, int out_size)
{
    const float* X = (const float*)d_in[0];
    const float* Y = (const float*)d_in[1];
    float* out = (float*)d_out;
    (void)in_sizes; (void)n_in; (void)out_size;

    dim3 blk(32, 8);

    zero_acc_kernel<<<1, 64>>>();

    // Resolve scratch symbol addresses (host-side of __device__ vars).
    // Using the symbols directly in kernels; pools get raw pointers via
    // cudaGetSymbolAddress-free approach: launch pool kernels that write to
    // the device globals through wrapper kernels is overkill — instead we
    // pass pointers obtained below (cudaGetSymbolAddress does not allocate
    // and is graph-capture safe: it enqueues nothing).
    static float *pX1 = nullptr, *pY1 = nullptr, *pX2 = nullptr, *pY2 = nullptr,
                 *pX3 = nullptr, *pY3 = nullptr;
    if (!pX1) {
        cudaGetSymbolAddress((void**)&pX1, g_X1);
        cudaGetSymbolAddress((void**)&pY1, g_Y1);
        cudaGetSymbolAddress((void**)&pX2, g_X2);
        cudaGetSymbolAddress((void**)&pY2, g_Y2);
        cudaGetSymbolAddress((void**)&pX3, g_X3);
        cudaGetSymbolAddress((void**)&pY3, g_Y3);
    }

    // ---- Level 0: 512 -> out 502
    {
        int H = 512, oH = 502;
        int tiles = cdiv(oH, TILE);              // 16
        dim3 grid(tiles * tiles, NC, NB);
        ssim_level_kernel<<<grid, blk>>>(X, Y, H, H, oH, oH, tiles, 0, 0);
        int total = NB * NC * 256 * 256;
        pool2_kernel<<<cdiv(total, 256), 256>>>(X, Y, pX1, pY1, 512, 512);
    }
    // ---- Level 1: 256 -> out 246
    {
        int H = 256, oH = 246;
        int tiles = cdiv(oH, TILE);              // 8
        dim3 grid(tiles * tiles, NC, NB);
        ssim_level_kernel<<<grid, blk>>>(pX1, pY1, H, H, oH, oH, tiles, 1, 0);
        int total = NB * NC * 128 * 128;
        pool2_kernel<<<cdiv(total, 256), 256>>>(pX1, pY1, pX2, pY2, 256, 256);
    }
    // ---- Level 2: 128 -> out 118
    {
        int H = 128, oH = 118;
        int tiles = cdiv(oH, TILE);              // 4
        dim3 grid(tiles * tiles, NC, NB);
        ssim_level_kernel<<<grid, blk>>>(pX2, pY2, H, H, oH, oH, tiles, 2, 0);
        int total = NB * NC * 64 * 64;
        pool2_kernel<<<cdiv(total, 256), 256>>>(pX2, pY2, pX3, pY3, 128, 128);
    }
    // ---- Level 3: 64 -> out 54 (last: ssim map, not just cs)
    {
        int H = 64, oH = 54;
        int tiles = cdiv(oH, TILE);              // 2
        dim3 grid(tiles * tiles, NC, NB);
        ssim_level_kernel<<<grid, blk>>>(pX3, pY3, H, H, oH, oH, tiles, 3, 1);
    }

    finalize_kernel<<<1, 32>>>(out);
}

// round 3
// speedup vs baseline: 1.4085x; 1.4085x over previous
#include <cuda_runtime.h>

// ---------------------------------------------------------------------------
// MS-SSIM, 4 levels, 11-tap Gaussian (sigma=1.5), VALID padding.
// X, Y: [16, 3, 512, 512] fp32. Output: 16 fp32 (1 - ms_ssim per batch).
//
// R3 design: one fused kernel per level.
//  - 128-wide x 32-tall output tile per 128-thread block.
//  - Input halo tile (42 rows x 138 cols, x&y interleaved as float2) in smem.
//  - Each thread owns one output column: horizontal 11-tap sums per row from
//    smem, vertical 11-tap via a fully unrolled register ring (no smem
//    round-trip for blurred quantities).
//  - Packed fp32x2 math (fma.rn.f32x2) pairs (mu1,mu2) and (xx,yy).
//  - 2x2 avg-pool fused: each block pools its non-halo 32x128 input patch.
// ---------------------------------------------------------------------------

#define KW    11
#define TW    128            // tile output width
#define TH    32             // tile output height
#define IW    (TW + KW - 1)  // 138 input cols
#define IWP   140            // padded
#define IH    (TH + KW - 1)  // 42 input rows
#define NB    16
#define NC    3

__device__ double g_acc[4 * NB];
__device__ float g_X1[NB * NC * 256 * 256];
__device__ float g_Y1[NB * NC * 256 * 256];
__device__ float g_X2[NB * NC * 128 * 128];
__device__ float g_Y2[NB * NC * 128 * 128];
__device__ float g_X3[NB * NC * 64 * 64];
__device__ float g_Y3[NB * NC * 64 * 64];

// ---- packed f32x2 helpers (sm_103a) ----
typedef unsigned long long ull;

__device__ __forceinline__ ull pk2(float lo, float hi) {
    ull r; asm("mov.b64 %0,{%1,%2};" : "=l"(r) : "f"(lo), "f"(hi)); return r;
}
__device__ __forceinline__ void up2(ull v, float& lo, float& hi) {
    asm("mov.b64 {%0,%1},%2;" : "=f"(lo), "=f"(hi) : "l"(v));
}
__device__ __forceinline__ ull fma2(ull a, ull b, ull c) {
    ull d; asm("fma.rn.f32x2 %0,%1,%2,%3;" : "=l"(d) : "l"(a), "l"(b), "l"(c));
    return d;
}
__device__ __forceinline__ ull mul2(ull a, ull b) {
    ull d; asm("mul.rn.f32x2 %0,%1,%2;" : "=l"(d) : "l"(a), "l"(b));
    return d;
}

__global__ void zero_acc_kernel() {
    int i = threadIdx.x;
    if (i < 4 * NB) g_acc[i] = 0.0;
}

// Grid: (tilesX*tilesY, NC, NB), block: 128 threads.
__global__ __launch_bounds__(128) void ssim_level_kernel(
    const float* __restrict__ X, const float* __restrict__ Y,
    float* __restrict__ Xp, float* __restrict__ Yp,   // pooled outputs (or null)
    int H, int W, int outH, int outW, int tilesX,
    int level, int isLast, int doPool)
{
    __shared__ float2 sxy[IH][IWP];
    __shared__ float red[128];

    const int b = blockIdx.z;
    const int c = blockIdx.y;
    const int tile = blockIdx.x;
    const int tx = tile % tilesX;
    const int ty = tile / tilesX;
    const int ix0 = tx * TW;
    const int iy0 = ty * TH;
    const int tid = threadIdx.x;

    const size_t plane = (size_t)(b * NC + c) * H * W;
    const float* __restrict__ Xi = X + plane;
    const float* __restrict__ Yi = Y + plane;

    // ---- Phase 0: cooperative halo load (clamped) ----
    #pragma unroll 4
    for (int i = tid; i < IH * IW; i += 128) {
        int r  = i / IW;
        int cc = i - r * IW;
        int gy = min(iy0 + r,  H - 1);
        int gx = min(ix0 + cc, W - 1);
        int gi = gy * W + gx;
        sxy[r][cc] = make_float2(Xi[gi], Yi[gi]);
    }
    __syncthreads();

    // ---- Phase 1: per-column streaming with register ring ----
    const float G[KW] = {
        0.00102838f, 0.00759875f, 0.03600077f, 0.10936069f, 0.21300553f,
        0.26601174f,
        0.21300553f, 0.10936069f, 0.03600077f, 0.00759875f, 0.00102838f
    };
    const float C1 = 1e-4f;
    const float C2 = 9e-4f;

    ull  r01[KW];   // ring: (sum g*x, sum g*y)
    ull  r23[KW];   // ring: (sum g*x^2, sum g*y^2)
    float r4[KW];   // ring: sum g*x*y

    const int lx = tid;            // output column within tile
    const int ox = ix0 + lx;
    const bool colOK = (ox < outW);
    float local = 0.f;

    #pragma unroll
    for (int r = 0; r < IH; r++) {
        // horizontal 11-tap on row r
        const ull* __restrict__ row =
            reinterpret_cast<const ull*>(&sxy[r][lx]);
        ull s01, s23; float s4;
        {
            ull v = row[0];
            ull gg = pk2(G[0], G[0]);
            s01 = mul2(gg, v);
            ull t = mul2(gg, v);
            s23 = mul2(t, v);
            float xv, yv, tl, th;
            up2(v, xv, yv); up2(t, tl, th);
            s4 = tl * yv;
            (void)xv; (void)th;
        }
        #pragma unroll
        for (int k = 1; k < KW; k++) {
            ull v = row[k];
            ull gg = pk2(G[k], G[k]);
            s01 = fma2(gg, v, s01);
            ull t = mul2(gg, v);
            s23 = fma2(t, v, s23);
            float xv, yv, tl, th;
            up2(v, xv, yv); up2(t, tl, th);
            s4 = fmaf(tl, yv, s4);
            (void)xv; (void)th;
        }
        r01[r % KW] = s01;
        r23[r % KW] = s23;
        r4[r % KW]  = s4;

        if (r >= KW - 1) {
            const int orow = r - (KW - 1);     // output row within tile
            // vertical 11-tap over the ring
            ull m01, m23; float m4;
            {
                int idx = orow % KW;
                ull gg = pk2(G[0], G[0]);
                m01 = mul2(gg, r01[idx]);
                m23 = mul2(gg, r23[idx]);
                m4  = G[0] * r4[idx];
            }
            #pragma unroll
            for (int k = 1; k < KW; k++) {
                int idx = (orow + k) % KW;
                ull gg = pk2(G[k], G[k]);
                m01 = fma2(gg, r01[idx], m01);
                m23 = fma2(gg, r23[idx], m23);
                m4  = fmaf(G[k], r4[idx], m4);
            }
            int oy = iy0 + orow;
            if (colOK && oy < outH) {
                float mu1, mu2, xx, yy;
                up2(m01, mu1, mu2);
                up2(m23, xx, yy);
                float s1q = xx - mu1 * mu1;
                float s2q = yy - mu2 * mu2;
                float s12 = m4 - mu1 * mu2;
                float cs = __fdividef(2.f * s12 + C2, s1q + s2q + C2);
                cs = fmaxf(cs, 0.f);
                if (isLast) {
                    float lum = __fdividef(2.f * mu1 * mu2 + C1,
                                           mu1 * mu1 + mu2 * mu2 + C1);
                    local = fmaf(lum, cs, local);
                } else {
                    local += cs;
                }
            }
        }
    }

    // ---- Phase 2: fused 2x2 avg pool of this block's interior patch ----
    if (doPool) {
        const int oW = W >> 1;
        const int pgy0 = iy0 >> 1;          // 16 * ty
        const int pgx0 = ix0 >> 1;          // 64 * tx
        float* __restrict__ Xo = Xp + (size_t)(b * NC + c) * (oW * (H >> 1));
        float* __restrict__ Yo = Yp + (size_t)(b * NC + c) * (oW * (H >> 1));
        #pragma unroll
        for (int i = 0; i < 8; i++) {
            int idx = tid + i * 128;        // 0..1023
            int py = idx >> 6;              // 0..15
            int px = idx & 63;              // 0..63
            float2 a = sxy[2 * py][2 * px];
            float2 bb = sxy[2 * py][2 * px + 1];
            float2 cc2 = sxy[2 * py + 1][2 * px];
            float2 dd = sxy[2 * py + 1][2 * px + 1];
            float xv = 0.25f * (a.x + bb.x + cc2.x + dd.x);
            float yv = 0.25f * (a.y + bb.y + cc2.y + dd.y);
            size_t o = (size_t)(pgy0 + py) * oW + (pgx0 + px);
            Xo[o] = xv;
            Yo[o] = yv;
        }
    }

    // ---- Block reduction into g_acc ----
    // warp reduce first
    #pragma unroll
    for (int s = 16; s > 0; s >>= 1)
        local += __shfl_down_sync(0xffffffffu, local, s);
    if ((tid & 31) == 0) red[tid >> 5] = local;
    __syncthreads();
    if (tid == 0) {
        float t = red[0] + red[1] + red[2] + red[3];
        atomicAdd(&g_acc[level * NB + b], (double)t);
    }
}

__global__ void finalize_kernel(float* __restrict__ out) {
    int b = threadIdx.x;
    if (b >= NB) return;
    const double counts[4] = {
        3.0 * 502.0 * 502.0,
        3.0 * 246.0 * 246.0,
        3.0 * 118.0 * 118.0,
        3.0 * 54.0  * 54.0
    };
    const double wraw[4] = {0.0448, 0.2856, 0.3001, 0.2363};
    const double wsum = 0.0448 + 0.2856 + 0.3001 + 0.2363;
    double s = 0.0;
    #pragma unroll
    for (int l = 0; l < 4; l++) {
        double v = g_acc[l * NB + b] / counts[l];
        v = v > 1e-8 ? v : 1e-8;
        s += (wraw[l] / wsum) * log(v);
    }
    out[b] = (float)(1.0 - exp(s));
}

static inline int cdiv(int a, int b) { return (a + b - 1) / b; }

extern "C" void kernel_launch(void* const* d_in, const int* in_sizes, int n_in,
                              void* d_out, int out_size)
{
    const float* X = (const float*)d_in[0];
    const float* Y = (const float*)d_in[1];
    float* out = (float*)d_out;
    (void)in_sizes; (void)n_in; (void)out_size;

    static float *pX1 = nullptr, *pY1 = nullptr, *pX2 = nullptr, *pY2 = nullptr,
                 *pX3 = nullptr, *pY3 = nullptr;
    if (!pX1) {
        cudaGetSymbolAddress((void**)&pX1, g_X1);
        cudaGetSymbolAddress((void**)&pY1, g_Y1);
        cudaGetSymbolAddress((void**)&pX2, g_X2);
        cudaGetSymbolAddress((void**)&pY2, g_Y2);
        cudaGetSymbolAddress((void**)&pX3, g_X3);
        cudaGetSymbolAddress((void**)&pY3, g_Y3);
    }

    zero_acc_kernel<<<1, 64>>>();

    // Level 0: 512 -> out 502, pool to 256
    {
        int H = 512, oH = 502;
        int tX = cdiv(oH, TW), tY = cdiv(oH, TH);     // 4, 16
        dim3 grid(tX * tY, NC, NB);
        ssim_level_kernel<<<grid, 128>>>(X, Y, pX1, pY1,
                                         H, H, oH, oH, tX, 0, 0, 1);
    }
    // Level 1: 256 -> out 246, pool to 128
    {
        int H = 256, oH = 246;
        int tX = cdiv(oH, TW), tY = cdiv(oH, TH);     // 2, 8
        dim3 grid(tX * tY, NC, NB);
        ssim_level_kernel<<<grid, 128>>>(pX1, pY1, pX2, pY2,
                                         H, H, oH, oH, tX, 1, 0, 1);
    }
    // Level 2: 128 -> out 118, pool to 64
    {
        int H = 128, oH = 118;
        int tX = cdiv(oH, TW), tY = cdiv(oH, TH);     // 1, 4
        dim3 grid(tX * tY, NC, NB);
        ssim_level_kernel<<<grid, 128>>>(pX2, pY2, pX3, pY3,
                                         H, H, oH, oH, tX, 2, 0, 1);
    }
    // Level 3: 64 -> out 54, last (ssim map), no pool
    {
        int H = 64, oH = 54;
        int tX = cdiv(oH, TW), tY = cdiv(oH, TH);     // 1, 2
        dim3 grid(tX * tY, NC, NB);
        ssim_level_kernel<<<grid, 128>>>(pX3, pY3, nullptr, nullptr,
                                         H, H, oH, oH, tX, 3, 1, 0);
    }

    finalize_kernel<<<1, 32>>>(out);
}

// round 4
// speedup vs baseline: 1.6125x; 1.1448x over previous
#include <cuda_runtime.h>

// ---------------------------------------------------------------------------
// MS-SSIM, 4 levels, 11-tap Gaussian (sigma=1.5), VALID padding.
// X, Y: [16, 3, 512, 512] fp32. Output: 16 fp32 (1 - ms_ssim per batch).
//
// R4: per-level tile shapes (templated). Big levels: 128x32 tiles (best
// horizontal amortization). Small levels: 64x16 tiles (4x more blocks,
// shorter serial register-ring chain) to fix the latency-bound tail.
// ---------------------------------------------------------------------------

#define KW 11
#define NB 16
#define NC 3

__device__ double g_acc[4 * NB];
__device__ float g_X1[NB * NC * 256 * 256];
__device__ float g_Y1[NB * NC * 256 * 256];
__device__ float g_X2[NB * NC * 128 * 128];
__device__ float g_Y2[NB * NC * 128 * 128];
__device__ float g_X3[NB * NC * 64 * 64];
__device__ float g_Y3[NB * NC * 64 * 64];

typedef unsigned long long ull;

__device__ __forceinline__ ull pk2(float lo, float hi) {
    ull r; asm("mov.b64 %0,{%1,%2};" : "=l"(r) : "f"(lo), "f"(hi)); return r;
}
__device__ __forceinline__ void up2(ull v, float& lo, float& hi) {
    asm("mov.b64 {%0,%1},%2;" : "=f"(lo), "=f"(hi) : "l"(v));
}
__device__ __forceinline__ ull fma2(ull a, ull b, ull c) {
    ull d; asm("fma.rn.f32x2 %0,%1,%2,%3;" : "=l"(d) : "l"(a), "l"(b), "l"(c));
    return d;
}
__device__ __forceinline__ ull mul2(ull a, ull b) {
    ull d; asm("mul.rn.f32x2 %0,%1,%2;" : "=l"(d) : "l"(a), "l"(b));
    return d;
}

__global__ void zero_acc_kernel() {
    int i = threadIdx.x;
    if (i < 4 * NB) g_acc[i] = 0.0;
}

// Grid: (tilesX*tilesY, NC, NB), block: TW_ threads (one per output column).
template<int TW_, int TH_, bool LAST, bool POOL>
__global__ __launch_bounds__(TW_) void ssim_level_kernel(
    const float* __restrict__ X, const float* __restrict__ Y,
    float* __restrict__ Xp, float* __restrict__ Yp,
    int H, int W, int outH, int outW, int tilesX, int level)
{
    constexpr int IH_  = TH_ + KW - 1;
    constexpr int IW_  = TW_ + KW - 1;
    constexpr int IWP_ = TW_ + 12;          // even padding
    constexpr int NWARP = TW_ / 32;

    __shared__ float2 sxy[IH_][IWP_];
    __shared__ float red[NWARP];

    const int b = blockIdx.z;
    const int c = blockIdx.y;
    const int tile = blockIdx.x;
    const int tx = tile % tilesX;
    const int ty = tile / tilesX;
    const int ix0 = tx * TW_;
    const int iy0 = ty * TH_;
    const int tid = threadIdx.x;

    const size_t plane = (size_t)(b * NC + c) * H * W;
    const float* __restrict__ Xi = X + plane;
    const float* __restrict__ Yi = Y + plane;

    // ---- Phase 0: cooperative halo load (clamped) ----
    #pragma unroll 4
    for (int i = tid; i < IH_ * IW_; i += TW_) {
        int r  = i / IW_;
        int cc = i - r * IW_;
        int gy = min(iy0 + r,  H - 1);
        int gx = min(ix0 + cc, W - 1);
        int gi = gy * W + gx;
        sxy[r][cc] = make_float2(Xi[gi], Yi[gi]);
    }
    __syncthreads();

    const float G[KW] = {
        0.00102838f, 0.00759875f, 0.03600077f, 0.10936069f, 0.21300553f,
        0.26601174f,
        0.21300553f, 0.10936069f, 0.03600077f, 0.00759875f, 0.00102838f
    };
    const float C1 = 1e-4f;
    const float C2 = 9e-4f;

    ull   r01[KW];
    ull   r23[KW];
    float r4[KW];

    const int lx = tid;
    const int ox = ix0 + lx;
    const bool colOK = (ox < outW);
    float local = 0.f;

    #pragma unroll
    for (int r = 0; r < IH_; r++) {
        const ull* __restrict__ row =
            reinterpret_cast<const ull*>(&sxy[r][lx]);
        ull s01, s23; float s4;
        {
            ull v = row[0];
            ull gg = pk2(G[0], G[0]);
            s01 = mul2(gg, v);
            ull t = mul2(gg, v);
            s23 = mul2(t, v);
            float xv, yv, tl, th;
            up2(v, xv, yv); up2(t, tl, th);
            s4 = tl * yv;
            (void)xv; (void)th;
        }
        #pragma unroll
        for (int k = 1; k < KW; k++) {
            ull v = row[k];
            ull gg = pk2(G[k], G[k]);
            s01 = fma2(gg, v, s01);
            ull t = mul2(gg, v);
            s23 = fma2(t, v, s23);
            float xv, yv, tl, th;
            up2(v, xv, yv); up2(t, tl, th);
            s4 = fmaf(tl, yv, s4);
            (void)xv; (void)th;
        }
        r01[r % KW] = s01;
        r23[r % KW] = s23;
        r4[r % KW]  = s4;

        if (r >= KW - 1) {
            const int orow = r - (KW - 1);
            ull m01, m23; float m4;
            {
                int idx = orow % KW;
                ull gg = pk2(G[0], G[0]);
                m01 = mul2(gg, r01[idx]);
                m23 = mul2(gg, r23[idx]);
                m4  = G[0] * r4[idx];
            }
            #pragma unroll
            for (int k = 1; k < KW; k++) {
                int idx = (orow + k) % KW;
                ull gg = pk2(G[k], G[k]);
                m01 = fma2(gg, r01[idx], m01);
                m23 = fma2(gg, r23[idx], m23);
                m4  = fmaf(G[k], r4[idx], m4);
            }
            int oy = iy0 + orow;
            if (colOK && oy < outH) {
                float mu1, mu2, xx, yy;
                up2(m01, mu1, mu2);
                up2(m23, xx, yy);
                float s1q = xx - mu1 * mu1;
                float s2q = yy - mu2 * mu2;
                float s12 = m4 - mu1 * mu2;
                float cs = __fdividef(2.f * s12 + C2, s1q + s2q + C2);
                cs = fmaxf(cs, 0.f);
                if (LAST) {
                    float lum = __fdividef(2.f * mu1 * mu2 + C1,
                                           mu1 * mu1 + mu2 * mu2 + C1);
                    local = fmaf(lum, cs, local);
                } else {
                    local += cs;
                }
            }
        }
    }

    // ---- Phase 2: fused 2x2 avg pool of this block's interior patch ----
    if (POOL) {
        const int oW = W >> 1;
        const int pgy0 = iy0 >> 1;
        const int pgx0 = ix0 >> 1;
        constexpr int PW = TW_ / 2;
        constexpr int ITER = (TH_ / 2) * PW / TW_;   // TH_/4
        float* __restrict__ Xo = Xp + (size_t)(b * NC + c) * (oW * (H >> 1));
        float* __restrict__ Yo = Yp + (size_t)(b * NC + c) * (oW * (H >> 1));
        #pragma unroll
        for (int i = 0; i < ITER; i++) {
            int idx = tid + i * TW_;
            int py = idx / PW;
            int px = idx % PW;
            float2 a  = sxy[2 * py][2 * px];
            float2 bb = sxy[2 * py][2 * px + 1];
            float2 cc = sxy[2 * py + 1][2 * px];
            float2 dd = sxy[2 * py + 1][2 * px + 1];
            float xv = 0.25f * (a.x + bb.x + cc.x + dd.x);
            float yv = 0.25f * (a.y + bb.y + cc.y + dd.y);
            size_t o = (size_t)(pgy0 + py) * oW + (pgx0 + px);
            Xo[o] = xv;
            Yo[o] = yv;
        }
    }

    // ---- Block reduction ----
    #pragma unroll
    for (int s = 16; s > 0; s >>= 1)
        local += __shfl_down_sync(0xffffffffu, local, s);
    if ((tid & 31) == 0) red[tid >> 5] = local;
    __syncthreads();
    if (tid == 0) {
        float t = 0.f;
        #pragma unroll
        for (int w = 0; w < NWARP; w++) t += red[w];
        atomicAdd(&g_acc[level * NB + b], (double)t);
    }
}

__global__ void finalize_kernel(float* __restrict__ out) {
    int b = threadIdx.x;
    if (b >= NB) return;
    const double counts[4] = {
        3.0 * 502.0 * 502.0,
        3.0 * 246.0 * 246.0,
        3.0 * 118.0 * 118.0,
        3.0 * 54.0  * 54.0
    };
    const double wraw[4] = {0.0448, 0.2856, 0.3001, 0.2363};
    const double wsum = 0.0448 + 0.2856 + 0.3001 + 0.2363;
    double s = 0.0;
    #pragma unroll
    for (int l = 0; l < 4; l++) {
        double v = g_acc[l * NB + b] / counts[l];
        v = v > 1e-8 ? v : 1e-8;
        s += (wraw[l] / wsum) * log(v);
    }
    out[b] = (float)(1.0 - exp(s));
}

static inline int cdiv(int a, int b) { return (a + b - 1) / b; }

extern "C" void kernel_launch(void* const* d_in, const int* in_sizes, int n_in,
                              void* d_out, int out_size)
{
    const float* X = (const float*)d_in[0];
    const float* Y = (const float*)d_in[1];
    float* out = (float*)d_out;
    (void)in_sizes; (void)n_in; (void)out_size;

    static float *pX1 = nullptr, *pY1 = nullptr, *pX2 = nullptr, *pY2 = nullptr,
                 *pX3 = nullptr, *pY3 = nullptr;
    if (!pX1) {
        cudaGetSymbolAddress((void**)&pX1, g_X1);
        cudaGetSymbolAddress((void**)&pY1, g_Y1);
        cudaGetSymbolAddress((void**)&pX2, g_X2);
        cudaGetSymbolAddress((void**)&pY2, g_Y2);
        cudaGetSymbolAddress((void**)&pX3, g_X3);
        cudaGetSymbolAddress((void**)&pY3, g_Y3);
    }

    zero_acc_kernel<<<1, 64>>>();

    // Level 0: 512 -> out 502, pool to 256. Tiles 128x32.
    {
        int H = 512, oH = 502;
        int tX = cdiv(oH, 128), tY = cdiv(oH, 32);       // 4, 16
        dim3 grid(tX * tY, NC, NB);
        ssim_level_kernel<128, 32, false, true><<<grid, 128>>>(
            X, Y, pX1, pY1, H, H, oH, oH, tX, 0);
    }
    // Level 1: 256 -> out 246, pool to 128. Tiles 128x32.
    {
        int H = 256, oH = 246;
        int tX = cdiv(oH, 128), tY = cdiv(oH, 32);       // 2, 8
        dim3 grid(tX * tY, NC, NB);
        ssim_level_kernel<128, 32, false, true><<<grid, 128>>>(
            pX1, pY1, pX2, pY2, H, H, oH, oH, tX, 1);
    }
    // Level 2: 128 -> out 118, pool to 64. Tiles 64x16 (more blocks).
    {
        int H = 128, oH = 118;
        int tX = cdiv(oH, 64), tY = cdiv(oH, 16);        // 2, 8
        dim3 grid(tX * tY, NC, NB);
        ssim_level_kernel<64, 16, false, true><<<grid, 64>>>(
            pX2, pY2, pX3, pY3, H, H, oH, oH, tX, 2);
    }
    // Level 3: 64 -> out 54, last (ssim map), no pool. Tiles 64x16.
    {
        int H = 64, oH = 54;
        int tX = cdiv(oH, 64), tY = cdiv(oH, 16);        // 1, 4
        dim3 grid(tX * tY, NC, NB);
        ssim_level_kernel<64, 16, true, false><<<grid, 64>>>(
            pX3, pY3, nullptr, nullptr, H, H, oH, oH, tX, 3);
    }

    finalize_kernel<<<1, 32>>>(out);
}